// round 16
// baseline (speedup 1.0000x reference)
#include <cuda_runtime.h>
#include <cuda_fp16.h>
#include <cstdint>

// Problem constants (fixed by the reference)
#define Bn   4
#define Cn   128
#define HWn  16384      // 128*128
#define Pn   4096
#define Vn   32
#define PT   8          // points per block (1 warp per point)

// Scratch for transposed x in fp16: [B][HW][C] half = 16.8 MB (256B rows).
__device__ __align__(16) __half g_xt[(size_t)Bn * HWn * Cn];

// 16B gather load, read-only, no L1 allocation.
__device__ __forceinline__ uint4 ldg_na128(const uint4* p)
{
    uint4 r;
    asm volatile("ld.global.nc.L1::no_allocate.v4.u32 {%0,%1,%2,%3}, [%4];"
                 : "=r"(r.x), "=r"(r.y), "=r"(r.z), "=r"(r.w) : "l"(p));
    return r;
}

// ---------------------------------------------------------------------------
// Kernel 1: transpose + downconvert x [B,C,HW] fp32 -> g_xt [B,HW,C] fp16.
// ---------------------------------------------------------------------------
__global__ __launch_bounds__(256) void transpose_fp16_kernel(const float* __restrict__ x)
{
    __shared__ float tile[64][33];

    const int b   = blockIdx.z;
    const int hw0 = blockIdx.x * 32;
    const int c0  = blockIdx.y * 64;
    const int tx  = threadIdx.x;   // 0..31
    const int ty  = threadIdx.y;   // 0..7

    #pragma unroll
    for (int j = 0; j < 8; j++) {
        const int cl = ty + j * 8;
        tile[cl][tx] = x[((size_t)b * Cn + c0 + cl) * HWn + hw0 + tx];
    }
    __syncthreads();

    const int t = ty * 32 + tx;
    __half2* xt2 = reinterpret_cast<__half2*>(g_xt);
    #pragma unroll
    for (int j = 0; j < 4; j++) {
        const int idx  = j * 256 + t;          // 0..1023
        const int hw_l = idx >> 5;             // 0..31
        const int c2   = idx & 31;             // half2 index within 64-ch slab
        const float f0 = tile[c2 * 2][hw_l];
        const float f1 = tile[c2 * 2 + 1][hw_l];
        xt2[(((size_t)b * HWn + hw0 + hw_l) * Cn + c0) / 2 + c2] =
            __floats2half2_rn(f0, f1);
    }
}

// ---------------------------------------------------------------------------
// Kernel 2: gather + vote accumulate. ONE WARP PER POINT, LSU-minimal:
// group of 4 votes = 2 LDS.64 (2 votes' offsets + weights per half-warp)
//                  + 2 LDG.128 (lane covers 16B = 8 channels of its vote)
// -> 1.0 LSU instruction per vote (r12 body used 2.0). Bytes unchanged.
// Half-warp partials merged by shfl_xor(16) at the end.
// ---------------------------------------------------------------------------
__global__ __launch_bounds__(256, 7) void gather_kernel(
    const int*   __restrict__ vote_index,   // [32768, 32]
    const float* __restrict__ vote_weight,  // [32768, 32]
    const int*   __restrict__ inds,         // [B, P] int32
    float*       __restrict__ out)          // [B, C, P]
{
    __shared__ __align__(16) unsigned s_off[PT][Vn];  // hw*16 (uint4 row units)
    __shared__ __align__(16) unsigned s_w2[PT][Vn];   // half2(w,w) bits
    __shared__ float s_out[PT][132];

    const int b    = blockIdx.y;
    const int p0   = blockIdx.x * PT;
    const int t    = threadIdx.x;
    const int warp = t >> 5;
    const int lane = t & 31;
    const int vsel = lane >> 4;      // half-warp: which 2 votes of each group
    const int lh   = lane & 15;      // uint4 slot within the 256B row

    // Stage per-vote row offsets + weights (warp w stages point p0+w).
    {
        const int sph = inds[(size_t)b * Pn + p0 + warp];   // warp-uniform
        const int hw  = vote_index[(size_t)sph * Vn + lane];
        const float w = vote_weight[(size_t)sph * Vn + lane];
        const __half2 w2 = __float2half2_rn(w);
        s_off[warp][lane] = (unsigned)hw * 16u;
        s_w2[warp][lane]  = *reinterpret_cast<const unsigned*>(&w2);
    }
    __syncthreads();

    // Row = 128 halves = 256B = 16 uint4; lane lh owns channels 8lh..8lh+7.
    const uint4* xt = reinterpret_cast<const uint4*>(g_xt)
                    + (size_t)b * HWn * 16 + lh;

    float2 acc[4];   // 8 fp32 channels per lane
    #pragma unroll
    for (int k = 0; k < 4; k++) acc[k] = make_float2(0.f, 0.f);

    #pragma unroll
    for (int g = 0; g < Vn / 4; g++) {   // 8 groups x 4 votes
        // One LDS.64 gives this half-warp its 2 votes' offsets; one more the
        // weights. (2-way broadcast across halves.)
        const uint2 off2 = *reinterpret_cast<const uint2*>(&s_off[warp][g * 4 + vsel * 2]);
        const uint2 w2p  = *reinterpret_cast<const uint2*>(&s_w2[warp][g * 4 + vsel * 2]);
        const uint4 ra = ldg_na128(xt + off2.x);
        const uint4 rb = ldg_na128(xt + off2.y);
        const __half2 wa = *reinterpret_cast<const __half2*>(&w2p.x);
        const __half2 wb = *reinterpret_cast<const __half2*>(&w2p.y);

        __half2 h0 = __float2half2_rn(0.f);
        __half2 h1 = __float2half2_rn(0.f);
        __half2 h2 = __float2half2_rn(0.f);
        __half2 h3 = __float2half2_rn(0.f);
        h0 = __hfma2(*reinterpret_cast<const __half2*>(&ra.x), wa, h0);
        h1 = __hfma2(*reinterpret_cast<const __half2*>(&ra.y), wa, h1);
        h2 = __hfma2(*reinterpret_cast<const __half2*>(&ra.z), wa, h2);
        h3 = __hfma2(*reinterpret_cast<const __half2*>(&ra.w), wa, h3);
        h0 = __hfma2(*reinterpret_cast<const __half2*>(&rb.x), wb, h0);
        h1 = __hfma2(*reinterpret_cast<const __half2*>(&rb.y), wb, h1);
        h2 = __hfma2(*reinterpret_cast<const __half2*>(&rb.z), wb, h2);
        h3 = __hfma2(*reinterpret_cast<const __half2*>(&rb.w), wb, h3);

        const float2 f0 = __half22float2(h0);
        const float2 f1 = __half22float2(h1);
        const float2 f2 = __half22float2(h2);
        const float2 f3 = __half22float2(h3);
        acc[0].x += f0.x; acc[0].y += f0.y;
        acc[1].x += f1.x; acc[1].y += f1.y;
        acc[2].x += f2.x; acc[2].y += f2.y;
        acc[3].x += f3.x; acc[3].y += f3.y;
    }

    // Merge the two half-warps' vote partials (votes {0,1} + votes {2,3} mod 4).
    #pragma unroll
    for (int k = 0; k < 4; k++) {
        acc[k].x += __shfl_xor_sync(0xFFFFFFFFu, acc[k].x, 16);
        acc[k].y += __shfl_xor_sync(0xFFFFFFFFu, acc[k].y, 16);
    }

    // Lanes 0-15 hold the final 8 channels each -> write 2 float4s.
    if (vsel == 0) {
        *reinterpret_cast<float4*>(&s_out[warp][lh * 8]) =
            make_float4(acc[0].x, acc[0].y, acc[1].x, acc[1].y);
        *reinterpret_cast<float4*>(&s_out[warp][lh * 8 + 4]) =
            make_float4(acc[2].x, acc[2].y, acc[3].x, acc[3].y);
    }
    __syncthreads();

    // Write out [C][PT] tile: 8 consecutive p per c row.
    #pragma unroll
    for (int i = t; i < Cn * PT; i += 256) {
        const int c  = i >> 3;   // i / PT
        const int pl = i & 7;    // i % PT
        out[((size_t)b * Cn + c) * Pn + p0 + pl] = s_out[pl][c];
    }
}

// ---------------------------------------------------------------------------
// Launch (two default-stream launches: capture-safe, allocation-free)
// ---------------------------------------------------------------------------
extern "C" void kernel_launch(void* const* d_in, const int* in_sizes, int n_in,
                              void* d_out, int out_size)
{
    const float* x           = (const float*)d_in[0];   // [4,128,128,128]
    const int*   vote_index  = (const int*)d_in[1];     // [32768,32]
    const float* vote_weight = (const float*)d_in[2];   // [32768,32]
    const int*   inds        = (const int*)d_in[3];     // [4,4096] int32
    float*       out         = (float*)d_out;           // [4,128,4096]

    {
        dim3 grid(HWn / 32, Cn / 64, Bn);   // (512, 2, 4)
        dim3 block(32, 8);
        transpose_fp16_kernel<<<grid, block>>>(x);
    }
    {
        dim3 grid(Pn / PT, Bn);             // (512, 4) = 2048 blocks
        gather_kernel<<<grid, 256>>>(vote_index, vote_weight, inds, out);
    }
}

// round 17
// speedup vs baseline: 1.0125x; 1.0125x over previous
#include <cuda_runtime.h>
#include <cuda_fp16.h>
#include <cstdint>

// Problem constants (fixed by the reference)
#define Bn   4
#define Cn   128
#define HWn  16384      // 128*128
#define Pn   4096
#define Vn   32
#define PT   8          // points per block (1 warp per point)

// Split-plane fp16 scratch: plane A = channels 0..63, plane B = channels
// 64..127, each [B][HW][64] halves (128B rows). Two planes 8MB apart so the
// two 128B lines of one vote map to different LTS slices.
#define PLANE_HALF2 ((size_t)Bn * HWn * 32)   // half2 units per plane
#define PLANE_UINT2 ((size_t)Bn * HWn * 16)   // uint2 units per plane
__device__ __align__(16) __half g_xt[(size_t)2 * Bn * HWn * 64];

// Gather load: read-only, no L1 allocation (best measured variant).
__device__ __forceinline__ uint2 ldg_na(const uint2* p)
{
    uint2 r;
    asm volatile("ld.global.nc.L1::no_allocate.v2.u32 {%0,%1}, [%2];"
                 : "=r"(r.x), "=r"(r.y) : "l"(p));
    return r;
}

// ---------------------------------------------------------------------------
// Kernel 1: transpose + downconvert x [B,C,HW] fp32 -> split planes.
// DRAM-read bound (33.5MB); ~6.4us measured.
// ---------------------------------------------------------------------------
__global__ __launch_bounds__(256) void transpose_fp16_kernel(const float* __restrict__ x)
{
    __shared__ float tile[64][33];

    const int b   = blockIdx.z;
    const int hw0 = blockIdx.x * 32;
    const int c0  = blockIdx.y * 64;     // 0 or 64 -> plane select
    const int tx  = threadIdx.x;   // 0..31
    const int ty  = threadIdx.y;   // 0..7

    #pragma unroll
    for (int j = 0; j < 8; j++) {
        const int cl = ty + j * 8;
        tile[cl][tx] = x[((size_t)b * Cn + c0 + cl) * HWn + hw0 + tx];
    }
    __syncthreads();

    const int t = ty * 32 + tx;
    __half2* xt2 = reinterpret_cast<__half2*>(g_xt) + (c0 >= 64 ? PLANE_HALF2 : 0);
    #pragma unroll
    for (int j = 0; j < 4; j++) {
        const int idx  = j * 256 + t;          // 0..1023
        const int hw_l = idx >> 5;             // 0..31
        const int c2   = idx & 31;             // half2 index within 64-ch row
        const float f0 = tile[c2 * 2][hw_l];
        const float f1 = tile[c2 * 2 + 1][hw_l];
        xt2[((size_t)b * HWn + hw0 + hw_l) * 32 + c2] = __floats2half2_rn(f0, f1);
    }
}

// ---------------------------------------------------------------------------
// Kernel 2: gather + vote accumulate. ONE WARP PER POINT. (round-12 best:
// 16.2us — the measured L1tex wavefront floor for 134MB of random 256B rows.)
// Lane l reads channels 4l..4l+3 via one LDG.64-na; fp16 HFMA2 partials
// flushed to fp32 every 4 votes; occ-8 launch bounds (32 regs).
// ---------------------------------------------------------------------------
__global__ __launch_bounds__(256, 8) void gather_kernel(
    const int*   __restrict__ vote_index,   // [32768, 32]
    const float* __restrict__ vote_weight,  // [32768, 32]
    const int*   __restrict__ inds,         // [B, P] int32
    float*       __restrict__ out)          // [B, C, P]
{
    __shared__ uint2 s_iw[PT][Vn];   // {hw * 16 (uint2 row offset), half2(w,w)}
    __shared__ float s_out[PT][132];

    const int b    = blockIdx.y;
    const int p0   = blockIdx.x * PT;
    const int t    = threadIdx.x;
    const int warp = t >> 5;
    const int lane = t & 31;

    // Stage fused (row offset in uint2 units, weight half2) per vote.
    {
        const int sph = inds[(size_t)b * Pn + p0 + warp];   // warp-uniform
        const int hw  = vote_index[(size_t)sph * Vn + lane];
        const float w = vote_weight[(size_t)sph * Vn + lane];
        const __half2 w2 = __float2half2_rn(w);
        s_iw[warp][lane] = make_uint2((unsigned)hw * 16u,
                                      *reinterpret_cast<const unsigned*>(&w2));
    }
    __syncthreads();

    // Per-lane base: plane select + batch base + lane slot within 16-uint2 row.
    const uint2* xt = reinterpret_cast<const uint2*>(g_xt)
                    + (lane >= 16 ? PLANE_UINT2 : 0)
                    + (size_t)b * HWn * 16
                    + (lane & 15);

    float2 accA = make_float2(0.f, 0.f);
    float2 accB = make_float2(0.f, 0.f);

    #pragma unroll
    for (int g = 0; g < Vn / 4; g++) {           // 8 groups of 4 votes
        const uint2 iw0 = s_iw[warp][g * 4 + 0];
        const uint2 iw1 = s_iw[warp][g * 4 + 1];
        const uint2 iw2 = s_iw[warp][g * 4 + 2];
        const uint2 iw3 = s_iw[warp][g * 4 + 3];
        const uint2 r0 = ldg_na(xt + iw0.x);
        const uint2 r1 = ldg_na(xt + iw1.x);
        const uint2 r2 = ldg_na(xt + iw2.x);
        const uint2 r3 = ldg_na(xt + iw3.x);

        __half2 h0 = __float2half2_rn(0.f);
        __half2 h1 = __float2half2_rn(0.f);
        h0 = __hfma2(*reinterpret_cast<const __half2*>(&r0.x),
                     *reinterpret_cast<const __half2*>(&iw0.y), h0);
        h1 = __hfma2(*reinterpret_cast<const __half2*>(&r0.y),
                     *reinterpret_cast<const __half2*>(&iw0.y), h1);
        h0 = __hfma2(*reinterpret_cast<const __half2*>(&r1.x),
                     *reinterpret_cast<const __half2*>(&iw1.y), h0);
        h1 = __hfma2(*reinterpret_cast<const __half2*>(&r1.y),
                     *reinterpret_cast<const __half2*>(&iw1.y), h1);
        h0 = __hfma2(*reinterpret_cast<const __half2*>(&r2.x),
                     *reinterpret_cast<const __half2*>(&iw2.y), h0);
        h1 = __hfma2(*reinterpret_cast<const __half2*>(&r2.y),
                     *reinterpret_cast<const __half2*>(&iw2.y), h1);
        h0 = __hfma2(*reinterpret_cast<const __half2*>(&r3.x),
                     *reinterpret_cast<const __half2*>(&iw3.y), h0);
        h1 = __hfma2(*reinterpret_cast<const __half2*>(&r3.y),
                     *reinterpret_cast<const __half2*>(&iw3.y), h1);

        const float2 f0 = __half22float2(h0);
        const float2 f1 = __half22float2(h1);
        accA.x += f0.x; accA.y += f0.y;
        accB.x += f1.x; accB.y += f1.y;
    }

    // Lane l holds channels 4l..4l+3 (plane split preserves this mapping).
    *reinterpret_cast<float4*>(&s_out[warp][lane * 4]) =
        make_float4(accA.x, accA.y, accB.x, accB.y);
    __syncthreads();

    // Write out [C][PT] tile: 8 consecutive p per c row.
    #pragma unroll
    for (int i = t; i < Cn * PT; i += 256) {
        const int c  = i >> 3;   // i / PT
        const int pl = i & 7;    // i % PT
        out[((size_t)b * Cn + c) * Pn + p0 + pl] = s_out[pl][c];
    }
}

// ---------------------------------------------------------------------------
// Launch (two default-stream launches: capture-safe, allocation-free)
// ---------------------------------------------------------------------------
extern "C" void kernel_launch(void* const* d_in, const int* in_sizes, int n_in,
                              void* d_out, int out_size)
{
    const float* x           = (const float*)d_in[0];   // [4,128,128,128]
    const int*   vote_index  = (const int*)d_in[1];     // [32768,32]
    const float* vote_weight = (const float*)d_in[2];   // [32768,32]
    const int*   inds        = (const int*)d_in[3];     // [4,4096] int32
    float*       out         = (float*)d_out;           // [4,128,4096]

    {
        dim3 grid(HWn / 32, Cn / 64, Bn);   // (512, 2, 4)
        dim3 block(32, 8);
        transpose_fp16_kernel<<<grid, block>>>(x);
    }
    {
        dim3 grid(Pn / PT, Bn);             // (512, 4) = 2048 blocks
        gather_kernel<<<grid, 256>>>(vote_index, vote_weight, inds, out);
    }
}